// round 12
// baseline (speedup 1.0000x reference)
#include <cuda_runtime.h>
#include <cuda_fp16.h>
#include <cstdint>

#define TOKENS   64
#define IN_F     4096
#define OUT_F    16384
#define TILE_M   128
#define KC       64
#define NCHUNK   (IN_F / KC)   // 64
#define NTHREADS 256

// ---- shared memory: two x tiles (fp16, 64 tokens x 64 k, SW128-swizzled rows) ----
#define SM_X0    0
#define SM_X1    8192
#define SM_TOTAL 16384

__device__ __forceinline__ uint32_t smem_u32(const void* p) {
    uint32_t a;
    asm("{ .reg .u64 t; cvta.to.shared.u64 t, %1; cvt.u32.u64 %0, t; }" : "=r"(a) : "l"(p));
    return a;
}

__device__ __forceinline__ uint32_t pack_i2h2(int a, int b) {
    __half2 h = __halves2half2(__int2half_rn(a), __int2half_rn(b));
    return *reinterpret_cast<uint32_t*>(&h);
}

__device__ __forceinline__ uint32_t pack_f2h2(float a, float b) {
    __half2 h = __floats2half2_rn(a, b);
    return *reinterpret_cast<uint32_t*>(&h);
}

#define LDSM_X4(r0, r1, r2, r3, addr)                                            \
    asm volatile("ldmatrix.sync.aligned.m8n8.x4.shared.b16 {%0,%1,%2,%3}, [%4];" \
                 : "=r"(r0), "=r"(r1), "=r"(r2), "=r"(r3) : "r"(addr))

#define MMA16816(d, a, b0, b1)                                               \
    asm volatile("mma.sync.aligned.m16n8k16.row.col.f32.f16.f16.f32 "        \
                 "{%0,%1,%2,%3}, {%4,%5,%6,%7}, {%8,%9}, {%0,%1,%2,%3};"     \
                 : "+f"((d)[0]), "+f"((d)[1]), "+f"((d)[2]), "+f"((d)[3])    \
                 : "r"((a)[0]), "r"((a)[1]), "r"((a)[2]), "r"((a)[3]),       \
                   "r"(b0), "r"(b1))

__global__ void __launch_bounds__(NTHREADS, 1)
w8a16_linear_kernel(const float* __restrict__ x, const int* __restrict__ w,
                    const float* __restrict__ sc, const float* __restrict__ bias,
                    float* __restrict__ out)
{
    extern __shared__ __align__(1024) char smem[];
    const uint32_t sb  = smem_u32(smem);
    const int tid = threadIdx.x;
    const int wid = tid >> 5;           // 8 warps, warp owns m16 rows
    const int lid = tid & 31;
    const int m0  = blockIdx.x * TILE_M;

    // ---- x staging (fp32 gmem -> fp16 smem, SW128-swizzled) ----
    const int xrow = tid >> 3;          // 0..31 (also covers xrow+32)
    const int xc   = tid & 7;           // 8-k granule
    const float4* xg4 = reinterpret_cast<const float4*>(x) + (size_t)xrow * (IN_F / 4) + xc * 2;
    const uint32_t xsts0 = sb + (uint32_t)(xrow * 128)
                         + (((uint32_t)(xc * 16)) ^ ((uint32_t)((xrow & 7) << 4)));

    // ---- B ldsm geometry (same as proven-working kernel) ----
    const uint32_t lxor = (uint32_t)((lid & 7) << 4);
    const uint32_t brow = (uint32_t)((((lid >> 4) & 1) * 8) + (lid & 7));
    const uint32_t bcol = (uint32_t)(((lid >> 3) & 1) * 16);

    // ---- A direct-from-gmem fragment addressing ----
    // m16n8k16 A frag: rows l/4 and l/4+8, k = {2c,2c+1} and {2c+8,2c+9}
    const int c = lid & 3;
    const int r = lid >> 2;
    const int* a0p = w + (size_t)(m0 + wid * 16 + r) * IN_F + c * 2;
    const int* a1p = a0p + 8 * IN_F;

    float acc[8][4];
    #pragma unroll
    for (int i = 0; i < 8; ++i)
        #pragma unroll
        for (int j = 0; j < 4; ++j) acc[i][j] = 0.0f;

    // ---- prologue: prefetch A chunk 0, stage x chunk 0 into buf0 ----
    int2 aw[16];
    #pragma unroll
    for (int s = 0; s < 4; ++s) {
        aw[s * 4 + 0] = *reinterpret_cast<const int2*>(a0p + s * 16);
        aw[s * 4 + 1] = *reinterpret_cast<const int2*>(a1p + s * 16);
        aw[s * 4 + 2] = *reinterpret_cast<const int2*>(a0p + s * 16 + 8);
        aw[s * 4 + 3] = *reinterpret_cast<const int2*>(a1p + s * 16 + 8);
    }
    a0p += KC; a1p += KC;

    {
        float4 f0 = xg4[0];
        float4 f1 = xg4[1];
        float4 f2 = xg4[32 * (IN_F / 4)];
        float4 f3 = xg4[32 * (IN_F / 4) + 1];
        xg4 += KC / 4;
        uint32_t h0 = pack_f2h2(f0.x, f0.y), h1 = pack_f2h2(f0.z, f0.w);
        uint32_t h2 = pack_f2h2(f1.x, f1.y), h3 = pack_f2h2(f1.z, f1.w);
        asm volatile("st.shared.v4.b32 [%0], {%1, %2, %3, %4};"
                     :: "r"(xsts0 + SM_X0), "r"(h0), "r"(h1), "r"(h2), "r"(h3) : "memory");
        uint32_t h4 = pack_f2h2(f2.x, f2.y), h5 = pack_f2h2(f2.z, f2.w);
        uint32_t h6 = pack_f2h2(f3.x, f3.y), h7 = pack_f2h2(f3.z, f3.w);
        asm volatile("st.shared.v4.b32 [%0], {%1, %2, %3, %4};"
                     :: "r"(xsts0 + SM_X0 + 4096u), "r"(h4), "r"(h5), "r"(h6), "r"(h7) : "memory");
    }
    __syncthreads();

    #pragma unroll 1
    for (int k = 0; k < NCHUNK; ++k) {
        // convert current A ints -> fp16 fragments (frees aw for the prefetch)
        uint32_t af[4][4];
        #pragma unroll
        for (int s = 0; s < 4; ++s)
            #pragma unroll
            for (int j = 0; j < 4; ++j)
                af[s][j] = pack_i2h2(aw[s * 4 + j].x, aw[s * 4 + j].y);

        // prefetch chunk k+1 (A into aw, x into nx*) — in flight during MMA below
        float4 nx0, nx1, nx2, nx3;
        if (k + 1 < NCHUNK) {
            #pragma unroll
            for (int s = 0; s < 4; ++s) {
                aw[s * 4 + 0] = *reinterpret_cast<const int2*>(a0p + s * 16);
                aw[s * 4 + 1] = *reinterpret_cast<const int2*>(a1p + s * 16);
                aw[s * 4 + 2] = *reinterpret_cast<const int2*>(a0p + s * 16 + 8);
                aw[s * 4 + 3] = *reinterpret_cast<const int2*>(a1p + s * 16 + 8);
            }
            a0p += KC; a1p += KC;
            nx0 = xg4[0];
            nx1 = xg4[1];
            nx2 = xg4[32 * (IN_F / 4)];
            nx3 = xg4[32 * (IN_F / 4) + 1];
            xg4 += KC / 4;
        }

        // MMA over this chunk: all 8 warps, warp = m16 x n64
        const uint32_t xbase = sb + ((k & 1) ? (uint32_t)SM_X1 : (uint32_t)SM_X0);
        #pragma unroll
        for (int s = 0; s < 4; ++s) {
            uint32_t bf[4][4];
            #pragma unroll
            for (int tg = 0; tg < 4; ++tg) {
                uint32_t addr = xbase + (brow + (uint32_t)(tg * 16)) * 128u
                              + (((uint32_t)(s * 32) + bcol) ^ lxor);
                LDSM_X4(bf[tg][0], bf[tg][1], bf[tg][2], bf[tg][3], addr);
            }
            #pragma unroll
            for (int tg = 0; tg < 4; ++tg) {
                MMA16816(acc[tg * 2],     af[s], bf[tg][0], bf[tg][1]);
                MMA16816(acc[tg * 2 + 1], af[s], bf[tg][2], bf[tg][3]);
            }
        }

        // stage x chunk k+1 into the other buffer
        if (k + 1 < NCHUNK) {
            const uint32_t nbase = ((k + 1) & 1) ? (uint32_t)SM_X1 : (uint32_t)SM_X0;
            uint32_t h0 = pack_f2h2(nx0.x, nx0.y), h1 = pack_f2h2(nx0.z, nx0.w);
            uint32_t h2 = pack_f2h2(nx1.x, nx1.y), h3 = pack_f2h2(nx1.z, nx1.w);
            asm volatile("st.shared.v4.b32 [%0], {%1, %2, %3, %4};"
                         :: "r"(xsts0 + nbase), "r"(h0), "r"(h1), "r"(h2), "r"(h3) : "memory");
            uint32_t h4 = pack_f2h2(nx2.x, nx2.y), h5 = pack_f2h2(nx2.z, nx2.w);
            uint32_t h6 = pack_f2h2(nx3.x, nx3.y), h7 = pack_f2h2(nx3.z, nx3.w);
            asm volatile("st.shared.v4.b32 [%0], {%1, %2, %3, %4};"
                         :: "r"(xsts0 + nbase + 4096u), "r"(h4), "r"(h5), "r"(h6), "r"(h7) : "memory");
            __syncthreads();
        }
    }

    // ---- epilogue: scale + bias, fp32 out ----
    {
        const int grp  = lid >> 2;
        const int q    = lid & 3;
        const int mloc = wid * 16 + grp;             // rows mloc and mloc+8
        const float s0  = sc[m0 + mloc];
        const float bb0 = bias[m0 + mloc];
        const float s1  = sc[m0 + mloc + 8];
        const float bb1 = bias[m0 + mloc + 8];
        float* o0 = out + (m0 + mloc);
        float* o1 = o0 + 8;
        #pragma unroll
        for (int nt = 0; nt < 8; ++nt) {
            const int t = nt * 8 + q * 2;
            o0[(size_t)t * OUT_F]       = acc[nt][0] * s0 + bb0;
            o0[(size_t)(t + 1) * OUT_F] = acc[nt][1] * s0 + bb0;
            o1[(size_t)t * OUT_F]       = acc[nt][2] * s1 + bb1;
            o1[(size_t)(t + 1) * OUT_F] = acc[nt][3] * s1 + bb1;
        }
    }
}

extern "C" void kernel_launch(void* const* d_in, const int* in_sizes, int n_in,
                              void* d_out, int out_size) {
    const float* x    = (const float*)d_in[0];
    const int*   w    = (const int*)d_in[1];
    const float* sc   = (const float*)d_in[2];
    const float* bias = (const float*)d_in[3];

    w8a16_linear_kernel<<<OUT_F / TILE_M, NTHREADS, SM_TOTAL>>>(x, w, sc, bias, (float*)d_out);
}

// round 13
// speedup vs baseline: 1.0027x; 1.0027x over previous
#include <cuda_runtime.h>
#include <cuda_fp16.h>
#include <cstdint>

#define TOKENS   64
#define IN_F     4096
#define OUT_F    16384
#define TILE_M   128
#define KC       64
#define NCHUNK   (IN_F / KC)   // 64
#define NTHREADS 256

// ---- shared memory: two x tiles (fp16, 64 tokens x 64 k, SW128-swizzled rows) ----
#define SM_X0    0
#define SM_X1    8192
#define SM_TOTAL 16384

__device__ __forceinline__ uint32_t smem_u32(const void* p) {
    uint32_t a;
    asm("{ .reg .u64 t; cvta.to.shared.u64 t, %1; cvt.u32.u64 %0, t; }" : "=r"(a) : "l"(p));
    return a;
}

__device__ __forceinline__ uint32_t pack_i2h2(int a, int b) {
    __half2 h = __halves2half2(__int2half_rn(a), __int2half_rn(b));
    return *reinterpret_cast<uint32_t*>(&h);
}

__device__ __forceinline__ uint32_t pack_f2h2(float a, float b) {
    __half2 h = __floats2half2_rn(a, b);
    return *reinterpret_cast<uint32_t*>(&h);
}

#define LDSM_X4(r0, r1, r2, r3, addr)                                            \
    asm volatile("ldmatrix.sync.aligned.m8n8.x4.shared.b16 {%0,%1,%2,%3}, [%4];" \
                 : "=r"(r0), "=r"(r1), "=r"(r2), "=r"(r3) : "r"(addr))

#define MMA16816(d, a, b0, b1)                                               \
    asm volatile("mma.sync.aligned.m16n8k16.row.col.f32.f16.f16.f32 "        \
                 "{%0,%1,%2,%3}, {%4,%5,%6,%7}, {%8,%9}, {%0,%1,%2,%3};"     \
                 : "+f"((d)[0]), "+f"((d)[1]), "+f"((d)[2]), "+f"((d)[3])    \
                 : "r"((a)[0]), "r"((a)[1]), "r"((a)[2]), "r"((a)[3]),       \
                   "r"(b0), "r"(b1))

__global__ void __launch_bounds__(NTHREADS, 1)
w8a16_linear_kernel(const float* __restrict__ x, const int* __restrict__ w,
                    const float* __restrict__ sc, const float* __restrict__ bias,
                    float* __restrict__ out)
{
    extern __shared__ __align__(1024) char smem[];
    const uint32_t sb  = smem_u32(smem);
    const int tid = threadIdx.x;
    const int wid = tid >> 5;           // 8 warps, warp owns m16 rows
    const int lid = tid & 31;
    const int m0  = blockIdx.x * TILE_M;

    // ---- x staging (fp32 gmem -> fp16 smem, SW128-swizzled) ----
    const int xrow = tid >> 3;          // 0..31 (also covers xrow+32)
    const int xc   = tid & 7;           // 8-k granule
    const float4* xg4 = reinterpret_cast<const float4*>(x) + (size_t)xrow * (IN_F / 4) + xc * 2;
    const uint32_t xsts0 = sb + (uint32_t)(xrow * 128)
                         + (((uint32_t)(xc * 16)) ^ ((uint32_t)((xrow & 7) << 4)));

    // ---- B ldsm geometry (same as proven-working kernel) ----
    const uint32_t lxor = (uint32_t)((lid & 7) << 4);
    const uint32_t brow = (uint32_t)((((lid >> 4) & 1) * 8) + (lid & 7));
    const uint32_t bcol = (uint32_t)(((lid >> 3) & 1) * 16);

    // ---- A direct-from-gmem fragment addressing ----
    // m16n8k16 A frag: rows l/4 and l/4+8, k = {2c,2c+1} and {2c+8,2c+9}
    const int c = lid & 3;
    const int r = lid >> 2;
    const int* a0p = w + (size_t)(m0 + wid * 16 + r) * IN_F + c * 2;
    const int* a1p = a0p + 8 * IN_F;

    float acc[8][4];
    #pragma unroll
    for (int i = 0; i < 8; ++i)
        #pragma unroll
        for (int j = 0; j < 4; ++j) acc[i][j] = 0.0f;

    // ---- prologue: prefetch A chunk 0, stage x chunk 0 into buf0 ----
    int2 aw[16];
    #pragma unroll
    for (int s = 0; s < 4; ++s) {
        aw[s * 4 + 0] = *reinterpret_cast<const int2*>(a0p + s * 16);
        aw[s * 4 + 1] = *reinterpret_cast<const int2*>(a1p + s * 16);
        aw[s * 4 + 2] = *reinterpret_cast<const int2*>(a0p + s * 16 + 8);
        aw[s * 4 + 3] = *reinterpret_cast<const int2*>(a1p + s * 16 + 8);
    }
    a0p += KC; a1p += KC;

    {
        float4 f0 = xg4[0];
        float4 f1 = xg4[1];
        float4 f2 = xg4[32 * (IN_F / 4)];
        float4 f3 = xg4[32 * (IN_F / 4) + 1];
        xg4 += KC / 4;
        uint32_t h0 = pack_f2h2(f0.x, f0.y), h1 = pack_f2h2(f0.z, f0.w);
        uint32_t h2 = pack_f2h2(f1.x, f1.y), h3 = pack_f2h2(f1.z, f1.w);
        asm volatile("st.shared.v4.b32 [%0], {%1, %2, %3, %4};"
                     :: "r"(xsts0 + SM_X0), "r"(h0), "r"(h1), "r"(h2), "r"(h3) : "memory");
        uint32_t h4 = pack_f2h2(f2.x, f2.y), h5 = pack_f2h2(f2.z, f2.w);
        uint32_t h6 = pack_f2h2(f3.x, f3.y), h7 = pack_f2h2(f3.z, f3.w);
        asm volatile("st.shared.v4.b32 [%0], {%1, %2, %3, %4};"
                     :: "r"(xsts0 + SM_X0 + 4096u), "r"(h4), "r"(h5), "r"(h6), "r"(h7) : "memory");
    }
    __syncthreads();

    #pragma unroll 1
    for (int k = 0; k < NCHUNK; ++k) {
        // convert current A ints -> fp16 fragments (frees aw for the prefetch)
        uint32_t af[4][4];
        #pragma unroll
        for (int s = 0; s < 4; ++s)
            #pragma unroll
            for (int j = 0; j < 4; ++j)
                af[s][j] = pack_i2h2(aw[s * 4 + j].x, aw[s * 4 + j].y);

        // prefetch chunk k+1 (A into aw, x into nx*) — in flight during MMA below
        float4 nx0, nx1, nx2, nx3;
        if (k + 1 < NCHUNK) {
            #pragma unroll
            for (int s = 0; s < 4; ++s) {
                aw[s * 4 + 0] = *reinterpret_cast<const int2*>(a0p + s * 16);
                aw[s * 4 + 1] = *reinterpret_cast<const int2*>(a1p + s * 16);
                aw[s * 4 + 2] = *reinterpret_cast<const int2*>(a0p + s * 16 + 8);
                aw[s * 4 + 3] = *reinterpret_cast<const int2*>(a1p + s * 16 + 8);
            }
            a0p += KC; a1p += KC;
            nx0 = xg4[0];
            nx1 = xg4[1];
            nx2 = xg4[32 * (IN_F / 4)];
            nx3 = xg4[32 * (IN_F / 4) + 1];
            xg4 += KC / 4;
        }

        // MMA over this chunk: all 8 warps, warp = m16 x n64
        const uint32_t xbase = sb + ((k & 1) ? (uint32_t)SM_X1 : (uint32_t)SM_X0);
        #pragma unroll
        for (int s = 0; s < 4; ++s) {
            uint32_t bf[4][4];
            #pragma unroll
            for (int tg = 0; tg < 4; ++tg) {
                uint32_t addr = xbase + (brow + (uint32_t)(tg * 16)) * 128u
                              + (((uint32_t)(s * 32) + bcol) ^ lxor);
                LDSM_X4(bf[tg][0], bf[tg][1], bf[tg][2], bf[tg][3], addr);
            }
            #pragma unroll
            for (int tg = 0; tg < 4; ++tg) {
                MMA16816(acc[tg * 2],     af[s], bf[tg][0], bf[tg][1]);
                MMA16816(acc[tg * 2 + 1], af[s], bf[tg][2], bf[tg][3]);
            }
        }

        // stage x chunk k+1 into the other buffer
        if (k + 1 < NCHUNK) {
            const uint32_t nbase = ((k + 1) & 1) ? (uint32_t)SM_X1 : (uint32_t)SM_X0;
            uint32_t h0 = pack_f2h2(nx0.x, nx0.y), h1 = pack_f2h2(nx0.z, nx0.w);
            uint32_t h2 = pack_f2h2(nx1.x, nx1.y), h3 = pack_f2h2(nx1.z, nx1.w);
            asm volatile("st.shared.v4.b32 [%0], {%1, %2, %3, %4};"
                         :: "r"(xsts0 + nbase), "r"(h0), "r"(h1), "r"(h2), "r"(h3) : "memory");
            uint32_t h4 = pack_f2h2(nx2.x, nx2.y), h5 = pack_f2h2(nx2.z, nx2.w);
            uint32_t h6 = pack_f2h2(nx3.x, nx3.y), h7 = pack_f2h2(nx3.z, nx3.w);
            asm volatile("st.shared.v4.b32 [%0], {%1, %2, %3, %4};"
                         :: "r"(xsts0 + nbase + 4096u), "r"(h4), "r"(h5), "r"(h6), "r"(h7) : "memory");
            __syncthreads();
        }
    }

    // ---- epilogue: scale + bias, fp32 out ----
    {
        const int grp  = lid >> 2;
        const int q    = lid & 3;
        const int mloc = wid * 16 + grp;             // rows mloc and mloc+8
        const float s0  = sc[m0 + mloc];
        const float bb0 = bias[m0 + mloc];
        const float s1  = sc[m0 + mloc + 8];
        const float bb1 = bias[m0 + mloc + 8];
        float* o0 = out + (m0 + mloc);
        float* o1 = o0 + 8;
        #pragma unroll
        for (int nt = 0; nt < 8; ++nt) {
            const int t = nt * 8 + q * 2;
            o0[(size_t)t * OUT_F]       = acc[nt][0] * s0 + bb0;
            o0[(size_t)(t + 1) * OUT_F] = acc[nt][1] * s0 + bb0;
            o1[(size_t)t * OUT_F]       = acc[nt][2] * s1 + bb1;
            o1[(size_t)(t + 1) * OUT_F] = acc[nt][3] * s1 + bb1;
        }
    }
}

extern "C" void kernel_launch(void* const* d_in, const int* in_sizes, int n_in,
                              void* d_out, int out_size) {
    const float* x    = (const float*)d_in[0];
    const int*   w    = (const int*)d_in[1];
    const float* sc   = (const float*)d_in[2];
    const float* bias = (const float*)d_in[3];

    w8a16_linear_kernel<<<OUT_F / TILE_M, NTHREADS, SM_TOTAL>>>(x, w, sc, bias, (float*)d_out);
}